// round 2
// baseline (speedup 1.0000x reference)
#include <cuda_runtime.h>
#include <math.h>

#define SEQ 2048
#define HID 1024
#define VOC 32000

// ---- static scratch (no allocations allowed) ----
__device__ float g_rnn_in[32 * 2048];
__device__ float g_h0[32 * 1024];
__device__ float g_cat[32 * 2048];          // [h1 | context]
__device__ float g_v[32 * 1024];
__device__ float g_vpart[8 * 32 * 1024];
__device__ float g_c[32];
__device__ float g_p[32 * 2048];
__device__ float g_pm[32 * 8];
__device__ float g_pl[32 * 8];
__device__ float g_pctx[32 * 8 * 1024];
__device__ float g_lm[32 * 4];
__device__ float g_ll[32 * 4];
__device__ float g_pi[8 * 32 * 3072];
__device__ float g_ph[8 * 32 * 3072];
__device__ float g_plog[4 * 32 * 32000];

// 1) embedding gather + concat with last_context -> g_rnn_in [32,2048]
__global__ void k_embed(const int* __restrict__ ids, const float* __restrict__ lctx,
                        const float* __restrict__ emb) {
    int idx = blockIdx.x * 256 + threadIdx.x;   // 65536
    int b = idx >> 11, j = idx & 2047;
    g_rnn_in[idx] = (j < HID) ? emb[(size_t)ids[b] * HID + j]
                              : lctx[b * HID + (j - HID)];
}

// 2) generic k-split GEMM: P[z][b][m] = sum_{k in slice z} A[m,k] * X[b,k]
//    BLOCK_M=128, 256 threads, 4x4 per-thread tile. M % 128 == 0, K % (32*ks) == 0.
__global__ __launch_bounds__(256) void k_gemm(const float* __restrict__ A,
        const float* __restrict__ Xext, int xsel, int M, int K, int ks, int dsel) {
    const float* X = (xsel == 0) ? Xext : (xsel == 1) ? g_rnn_in
                     : (xsel == 2) ? g_h0 : g_cat;
    float* P = (dsel == 0) ? g_pi : (dsel == 1) ? g_ph : g_plog;
    int z = blockIdx.y;
    int kc = K / ks, kb = z * kc;
    __shared__ float As[128 * 36];
    __shared__ float Xs[32 * 36];
    int tid = threadIdx.x;
    int tx = tid & 7, ty = tid >> 3;            // tx: 8 batch-groups of 4, ty: 32 row-groups
    int mb = blockIdx.x * 128;
    float acc[4][4] = {};
    for (int k0 = kb; k0 < kb + kc; k0 += 32) {
#pragma unroll
        for (int l = 0; l < 4; l++) {           // 1024 float4 -> A tile
            int idx = tid + 256 * l;
            int row = idx >> 3, q = idx & 7;
            float4 v = *reinterpret_cast<const float4*>(
                &A[(size_t)(mb + row) * K + k0 + q * 4]);
            *reinterpret_cast<float4*>(&As[row * 36 + q * 4]) = v;
        }
#pragma unroll
        for (int l = 0; l < 4; l++) {           // 1024 floats -> X tile [kk][b]
            int idx = tid + 256 * l;
            int b = idx >> 5, kk = idx & 31;
            Xs[kk * 36 + b] = X[(size_t)b * K + k0 + kk];
        }
        __syncthreads();
#pragma unroll
        for (int kk = 0; kk < 32; kk++) {
            float4 x = *reinterpret_cast<const float4*>(&Xs[kk * 36 + tx * 4]);
#pragma unroll
            for (int j = 0; j < 4; j++) {
                float a = As[(ty + 32 * j) * 36 + kk];
                acc[j][0] += a * x.x; acc[j][1] += a * x.y;
                acc[j][2] += a * x.z; acc[j][3] += a * x.w;
            }
        }
        __syncthreads();
    }
    float* Pz = P + (size_t)z * 32 * M;
#pragma unroll
    for (int j = 0; j < 4; j++) {
        int row = mb + ty + 32 * j;
#pragma unroll
        for (int i = 0; i < 4; i++)
            Pz[(size_t)(tx * 4 + i) * M + row] = acc[j][i];
    }
}

// 3) GRU combine: sum k-split partials, apply gates
__global__ void k_gru(const float* __restrict__ bih, const float* __restrict__ bhh,
                      const float* __restrict__ hprev, int ks, int layer,
                      float* __restrict__ dout) {
    int idx = blockIdx.x * 256 + threadIdx.x;   // 32768
    int b = idx >> 10, h = idx & 1023;
    const int M = 3072;
    float ir = bih[h], iz = bih[1024 + h], in = bih[2048 + h];
    float hr = bhh[h], hz = bhh[1024 + h], hn = bhh[2048 + h];
    for (int z = 0; z < ks; z++) {
        const float* pi = g_pi + (size_t)z * 32 * M + (size_t)b * M;
        const float* ph = g_ph + (size_t)z * 32 * M + (size_t)b * M;
        ir += pi[h]; iz += pi[1024 + h]; in += pi[2048 + h];
        hr += ph[h]; hz += ph[1024 + h]; hn += ph[2048 + h];
    }
    float r = 1.f / (1.f + __expf(-(ir + hr)));
    float zz = 1.f / (1.f + __expf(-(iz + hz)));
    float n = tanhf(in + r * hn);
    float out = (1.f - zz) * n + zz * hprev[b * 1024 + h];
    if (layer == 0) g_h0[idx] = out; else g_cat[b * 2048 + h] = out;
    dout[b * 1024 + h] = out;
}

// 4) v[b,k] = sum_j h1[b,j] * W_attn[j,k], j-chunked partials
__global__ __launch_bounds__(256) void k_vproj(const float* __restrict__ W) {
    __shared__ float xs[128 * 33];
    int tid = threadIdx.x;
    int jc = blockIdx.y;
    for (int l = 0; l < 16; l++) {
        int idx = tid + 256 * l;                // 4096
        int j = idx >> 5, b = idx & 31;
        xs[j * 33 + b] = g_cat[b * 2048 + jc * 128 + j];
    }
    __syncthreads();
    int k = blockIdx.x * 256 + tid;
    float acc[32] = {};
    for (int j = 0; j < 128; j++) {
        float w = W[(size_t)(jc * 128 + j) * 1024 + k];
#pragma unroll
        for (int b = 0; b < 32; b++) acc[b] += w * xs[j * 33 + b];
    }
#pragma unroll
    for (int b = 0; b < 32; b++)
        g_vpart[(size_t)jc * 32768 + b * 1024 + k] = acc[b];
}

__global__ void k_vreduce() {
    int idx = blockIdx.x * 256 + threadIdx.x;   // 32768
    float s = 0.f;
    for (int jc = 0; jc < 8; jc++) s += g_vpart[(size_t)jc * 32768 + idx];
    g_v[idx] = s;
}

// 5) c[b] = b_attn . h1[b]
__global__ void k_cvec(const float* __restrict__ ba) {
    int b = threadIdx.x >> 5, lane = threadIdx.x & 31;
    float acc = 0.f;
    for (int j = lane; j < 1024; j += 32) acc += ba[j] * g_cat[b * 2048 + j];
    for (int o = 16; o; o >>= 1) acc += __shfl_xor_sync(~0u, acc, o);
    if (!lane) g_c[b] = acc;
}

// 6) split-S attention: per (chunk, batch) scores + chunk softmax + ctx partial
__global__ __launch_bounds__(256) void k_attn(const float* __restrict__ enc) {
    int c = blockIdx.x, b = blockIdx.y;
    __shared__ float4 vs4[256];
    __shared__ float sc[256];
    __shared__ float red[1];
    int tid = threadIdx.x;
    vs4[tid] = reinterpret_cast<const float4*>(g_v + b * 1024)[tid];
    __syncthreads();
    int w = tid >> 5, lane = tid & 31;
    float4 vf[8];
#pragma unroll
    for (int j = 0; j < 8; j++) vf[j] = vs4[lane + 32 * j];
    float cb = g_c[b];
    const float4* enc4 = reinterpret_cast<const float4*>(enc);
    for (int i = 0; i < 32; i++) {
        int s = w * 32 + i;
        size_t base = ((size_t)b * SEQ + c * 256 + s) * 256;
        float acc = 0.f;
#pragma unroll
        for (int j = 0; j < 8; j++) {
            float4 e = enc4[base + lane + 32 * j];
            acc += e.x * vf[j].x + e.y * vf[j].y + e.z * vf[j].z + e.w * vf[j].w;
        }
        for (int o = 16; o; o >>= 1) acc += __shfl_xor_sync(~0u, acc, o);
        if (!lane) sc[s] = acc + cb;
    }
    __syncthreads();
    if (tid < 32) {
        float m = sc[tid];
        for (int j = 1; j < 8; j++) m = fmaxf(m, sc[tid + 32 * j]);
        for (int o = 16; o; o >>= 1) m = fmaxf(m, __shfl_xor_sync(~0u, m, o));
        if (!tid) red[0] = m;
    }
    __syncthreads();
    float m = red[0];
    float p = __expf(sc[tid] - m);
    g_p[b * SEQ + c * 256 + tid] = p;
    __syncthreads();
    sc[tid] = p;
    __syncthreads();
    if (tid < 32) {
        float l = 0.f;
        for (int j = 0; j < 8; j++) l += sc[tid + 32 * j];
        for (int o = 16; o; o >>= 1) l += __shfl_xor_sync(~0u, l, o);
        if (!tid) { g_pm[b * 8 + c] = m; g_pl[b * 8 + c] = l; }
    }
    float a0 = 0, a1 = 0, a2 = 0, a3 = 0;
    const float* eb = enc + ((size_t)b * SEQ + c * 256) * 1024;
    for (int s = 0; s < 256; s++) {
        float ps = sc[s];
        const float* row = eb + (size_t)s * 1024;
        a0 += ps * row[tid];       a1 += ps * row[tid + 256];
        a2 += ps * row[tid + 512]; a3 += ps * row[tid + 768];
    }
    size_t ci = (size_t)(b * 8 + c) * 1024;
    g_pctx[ci + tid] = a0;       g_pctx[ci + tid + 256] = a1;
    g_pctx[ci + tid + 512] = a2; g_pctx[ci + tid + 768] = a3;
}

// 7) attention combine: context + normalized weights
__global__ void k_attn_final(float* __restrict__ out_ctx, float* __restrict__ out_attn) {
    int b = blockIdx.x, tid = threadIdx.x;
    float M = g_pm[b * 8];
    for (int cc = 1; cc < 8; cc++) M = fmaxf(M, g_pm[b * 8 + cc]);
    float L = 0.f, f[8];
    for (int cc = 0; cc < 8; cc++) {
        f[cc] = __expf(g_pm[b * 8 + cc] - M);
        L += g_pl[b * 8 + cc] * f[cc];
    }
    float inv = 1.f / L;
    for (int q = 0; q < 4; q++) {
        int h = tid + 256 * q;
        float s = 0.f;
        for (int cc = 0; cc < 8; cc++)
            s += g_pctx[(size_t)(b * 8 + cc) * 1024 + h] * f[cc];
        s *= inv;
        out_ctx[b * 1024 + h] = s;
        g_cat[b * 2048 + 1024 + h] = s;
    }
    for (int s = tid; s < 2048; s += 256) {
        int cc = s >> 8;
        out_attn[b * 2048 + s] = g_p[b * 2048 + s] * f[cc] * inv;
    }
}

// 8) logits combine (+bias), chunked softmax
__global__ void k_lcomb(const float* __restrict__ bo, float* __restrict__ out) {
    int idx = blockIdx.x * 256 + threadIdx.x;   // 1,024,000
    int b = idx / 32000, m = idx - b * 32000;
    float s = bo[m];
    for (int z = 0; z < 4; z++)
        s += g_plog[(size_t)z * 1024000 + (size_t)b * 32000 + m];
    out[idx] = s;
}

__global__ void k_smax1(const float* __restrict__ logits) {
    int b = blockIdx.x, cc = blockIdx.y, tid = threadIdx.x;
    __shared__ float rs[256];
    const float* base = logits + (size_t)b * 32000 + cc * 8000;
    float m = -1e30f;
    for (int i = tid; i < 8000; i += 256) m = fmaxf(m, base[i]);
    rs[tid] = m; __syncthreads();
    for (int o = 128; o; o >>= 1) { if (tid < o) rs[tid] = fmaxf(rs[tid], rs[tid + o]); __syncthreads(); }
    m = rs[0]; __syncthreads();
    float l = 0.f;
    for (int i = tid; i < 8000; i += 256) l += __expf(base[i] - m);
    rs[tid] = l; __syncthreads();
    for (int o = 128; o; o >>= 1) { if (tid < o) rs[tid] += rs[tid + o]; __syncthreads(); }
    if (!tid) { g_lm[b * 4 + cc] = m; g_ll[b * 4 + cc] = rs[0]; }
}

__global__ void k_smax2(float* __restrict__ out) {
    int idx = blockIdx.x * 256 + threadIdx.x;
    int b = idx / 32000;
    float M = g_lm[b * 4];
    for (int cc = 1; cc < 4; cc++) M = fmaxf(M, g_lm[b * 4 + cc]);
    float L = 0.f;
    for (int cc = 0; cc < 4; cc++) L += g_ll[b * 4 + cc] * __expf(g_lm[b * 4 + cc] - M);
    out[idx] = __expf(out[idx] - M) / L;
}

extern "C" void kernel_launch(void* const* d_in, const int* in_sizes, int n_in,
                              void* d_out, int out_size) {
    const int*   ids  = (const int*)d_in[0];
    const float* lctx = (const float*)d_in[1];
    const float* hid  = (const float*)d_in[2];
    const float* enc  = (const float*)d_in[3];
    const float* emb  = (const float*)d_in[4];
    const float* Wat  = (const float*)d_in[5];
    const float* bat  = (const float*)d_in[6];
    const float* Wih0 = (const float*)d_in[7];
    const float* Whh0 = (const float*)d_in[8];
    const float* bih0 = (const float*)d_in[9];
    const float* bhh0 = (const float*)d_in[10];
    const float* Wih1 = (const float*)d_in[11];
    const float* Whh1 = (const float*)d_in[12];
    const float* bih1 = (const float*)d_in[13];
    const float* bhh1 = (const float*)d_in[14];
    const float* Wout = (const float*)d_in[15];
    const float* bout = (const float*)d_in[16];
    float* out    = (float*)d_out;
    float* o_sm   = out;                           // [32,32000]
    float* o_ctx  = out + 1024000;                 // [1,32,1024]
    float* o_hid  = out + 1024000 + 32768;         // [2,32,1024]
    float* o_attn = out + 1024000 + 32768 + 65536; // [32,1,2048]

    k_embed<<<256, 256>>>(ids, lctx, emb);
    k_gemm<<<dim3(24, 8), 256>>>(Wih0, nullptr, 1, 3072, 2048, 8, 0);
    k_gemm<<<dim3(24, 8), 256>>>(Whh0, hid, 0, 3072, 1024, 8, 1);
    k_gru<<<128, 256>>>(bih0, bhh0, hid, 8, 0, o_hid);
    k_gemm<<<dim3(24, 8), 256>>>(Wih1, nullptr, 2, 3072, 1024, 8, 0);
    k_gemm<<<dim3(24, 8), 256>>>(Whh1, hid + 32768, 0, 3072, 1024, 8, 1);
    k_gru<<<128, 256>>>(bih1, bhh1, hid + 32768, 8, 1, o_hid + 32768);
    k_vproj<<<dim3(4, 8), 256>>>(Wat);
    k_vreduce<<<128, 256>>>();
    k_cvec<<<1, 1024>>>(bat);
    k_attn<<<dim3(8, 32), 256>>>(enc);
    k_attn_final<<<32, 256>>>(o_ctx, o_attn);
    k_gemm<<<dim3(250, 4), 256>>>(Wout, nullptr, 3, 32000, 2048, 4, 2);
    k_lcomb<<<4000, 256>>>(bout, o_sm);
    k_smax1<<<dim3(32, 4), 256>>>(o_sm);
    k_smax2<<<4000, 256>>>(o_sm);
}

// round 4
// speedup vs baseline: 1.0867x; 1.0867x over previous
#include <cuda_runtime.h>
#include <math.h>

#define SEQ 2048
#define HID 1024
#define VOC 32000

// ---- static scratch ----
__device__ float g_rnn_in[32 * 2048];
__device__ float g_h0[32 * 1024];
__device__ float g_cat[32 * 2048];          // [h1 | context]
__device__ float g_v[32 * 1024];
__device__ float g_vpart[8 * 32 * 1024];
__device__ float g_c[32];
__device__ float g_p[32 * 2048];            // raw scores
__device__ float g_pm[32 * 8];
__device__ float g_pl[32 * 8];
__device__ float g_pctx[32 * 8 * 1024];
__device__ float g_lm[32 * 4];
__device__ float g_ll[32 * 4];
__device__ float g_pi[8 * 32 * 3072];
__device__ float g_ph[8 * 32 * 3072];
__device__ float g_plog[4 * 32 * 32000];

// ---- packed f32x2 helpers ----
__device__ __forceinline__ void fma2(unsigned long long& d, unsigned long long a,
                                     unsigned long long x) {
    asm("fma.rn.f32x2 %0, %1, %2, %0;" : "+l"(d) : "l"(a), "l"(x));
}
__device__ __forceinline__ unsigned long long pack2(float a) {
    unsigned long long r;
    asm("mov.b64 %0, {%1, %1};" : "=l"(r) : "f"(a));
    return r;
}
__device__ __forceinline__ void unpack2(unsigned long long v, float& lo, float& hi) {
    asm("mov.b64 {%0, %1}, %2;" : "=f"(lo), "=f"(hi) : "l"(v));
}

// 1) embedding gather + concat
__global__ void k_embed(const int* __restrict__ ids, const float* __restrict__ lctx,
                        const float* __restrict__ emb) {
    int idx = blockIdx.x * 256 + threadIdx.x;
    int b = idx >> 11, j = idx & 2047;
    g_rnn_in[idx] = (j < HID) ? emb[(size_t)ids[b] * HID + j]
                              : lctx[b * HID + (j - HID)];
}

// 2) k-split GEMM with f32x2: P[z][b][m] = sum_k A[m,k] X[b,k]
__global__ __launch_bounds__(256) void k_gemm(const float* __restrict__ A,
        const float* __restrict__ Xext, int xsel, int M, int K, int ks, int dsel) {
    const float* X = (xsel == 0) ? Xext : (xsel == 1) ? g_rnn_in
                     : (xsel == 2) ? g_h0 : g_cat;
    float* P = (dsel == 0) ? g_pi : (dsel == 1) ? g_ph : g_plog;
    int z = blockIdx.y;
    int kc = K / ks, kb = z * kc;
    __shared__ __align__(16) float As[128 * 36];
    __shared__ __align__(16) float Xs[32 * 36];
    int tid = threadIdx.x;
    int tx = tid & 7, ty = tid >> 3;
    int mb = blockIdx.x * 128;
    unsigned long long acc[4][2];
#pragma unroll
    for (int jj = 0; jj < 4; jj++) { acc[jj][0] = 0ull; acc[jj][1] = 0ull; }
    for (int k0 = kb; k0 < kb + kc; k0 += 32) {
#pragma unroll
        for (int l = 0; l < 4; l++) {
            int idx = tid + 256 * l;
            int row = idx >> 3, q = idx & 7;
            float4 v = *reinterpret_cast<const float4*>(
                &A[(size_t)(mb + row) * K + k0 + q * 4]);
            *reinterpret_cast<float4*>(&As[row * 36 + q * 4]) = v;
        }
#pragma unroll
        for (int l = 0; l < 4; l++) {
            int idx = tid + 256 * l;
            int b = idx >> 5, kk = idx & 31;
            Xs[kk * 36 + b] = X[(size_t)b * K + k0 + kk];
        }
        __syncthreads();
#pragma unroll
        for (int kk = 0; kk < 32; kk++) {
            unsigned long long x01 =
                *reinterpret_cast<const unsigned long long*>(&Xs[kk * 36 + tx * 4]);
            unsigned long long x23 =
                *reinterpret_cast<const unsigned long long*>(&Xs[kk * 36 + tx * 4 + 2]);
#pragma unroll
            for (int jj = 0; jj < 4; jj++) {
                unsigned long long a2 = pack2(As[(ty + 32 * jj) * 36 + kk]);
                fma2(acc[jj][0], a2, x01);
                fma2(acc[jj][1], a2, x23);
            }
        }
        __syncthreads();
    }
    float* Pz = P + (size_t)z * 32 * M;
#pragma unroll
    for (int jj = 0; jj < 4; jj++) {
        int row = mb + ty + 32 * jj;
        float v0, v1, v2, v3;
        unpack2(acc[jj][0], v0, v1);
        unpack2(acc[jj][1], v2, v3);
        Pz[(size_t)(tx * 4 + 0) * M + row] = v0;
        Pz[(size_t)(tx * 4 + 1) * M + row] = v1;
        Pz[(size_t)(tx * 4 + 2) * M + row] = v2;
        Pz[(size_t)(tx * 4 + 3) * M + row] = v3;
    }
}

// 3) GRU combine
__global__ void k_gru(const float* __restrict__ bih, const float* __restrict__ bhh,
                      const float* __restrict__ hprev, int ks, int layer,
                      float* __restrict__ dout) {
    int idx = blockIdx.x * 256 + threadIdx.x;
    int b = idx >> 10, h = idx & 1023;
    const int M = 3072;
    float ir = bih[h], iz = bih[1024 + h], in = bih[2048 + h];
    float hr = bhh[h], hz = bhh[1024 + h], hn = bhh[2048 + h];
    for (int z = 0; z < ks; z++) {
        const float* pi = g_pi + (size_t)z * 32 * M + (size_t)b * M;
        const float* ph = g_ph + (size_t)z * 32 * M + (size_t)b * M;
        ir += pi[h]; iz += pi[1024 + h]; in += pi[2048 + h];
        hr += ph[h]; hz += ph[1024 + h]; hn += ph[2048 + h];
    }
    float r = 1.f / (1.f + __expf(-(ir + hr)));
    float zz = 1.f / (1.f + __expf(-(iz + hz)));
    float n = tanhf(in + r * hn);
    float outv = (1.f - zz) * n + zz * hprev[b * 1024 + h];
    if (layer == 0) g_h0[idx] = outv; else g_cat[b * 2048 + h] = outv;
    dout[b * 1024 + h] = outv;
}

// 4) v = h1 @ W_attn (j-chunked, f32x2)
__global__ __launch_bounds__(256) void k_vproj(const float* __restrict__ W) {
    __shared__ __align__(16) float xs[128 * 34];
    int tid = threadIdx.x;
    int jc = blockIdx.y;
    for (int l = 0; l < 16; l++) {
        int idx = tid + 256 * l;
        int j = idx >> 5, b = idx & 31;
        xs[j * 34 + b] = g_cat[b * 2048 + jc * 128 + j];
    }
    __syncthreads();
    int k = blockIdx.x * 256 + tid;
    unsigned long long acc[16];
#pragma unroll
    for (int p = 0; p < 16; p++) acc[p] = 0ull;
    for (int j = 0; j < 128; j++) {
        unsigned long long w2 = pack2(W[(size_t)(jc * 128 + j) * 1024 + k]);
#pragma unroll
        for (int p = 0; p < 16; p++)
            fma2(acc[p], w2,
                 *reinterpret_cast<const unsigned long long*>(&xs[j * 34 + 2 * p]));
    }
#pragma unroll
    for (int p = 0; p < 16; p++) {
        float lo, hi;
        unpack2(acc[p], lo, hi);
        g_vpart[(size_t)jc * 32768 + (2 * p) * 1024 + k] = lo;
        g_vpart[(size_t)jc * 32768 + (2 * p + 1) * 1024 + k] = hi;
    }
}

__global__ void k_vreduce() {
    int idx = blockIdx.x * 256 + threadIdx.x;
    float s = 0.f;
    for (int jc = 0; jc < 8; jc++) s += g_vpart[(size_t)jc * 32768 + idx];
    g_v[idx] = s;
}

// 5) c[b] = b_attn . h1[b]
__global__ void k_cvec(const float* __restrict__ ba) {
    int b = threadIdx.x >> 5, lane = threadIdx.x & 31;
    float acc = 0.f;
    for (int j = lane; j < 1024; j += 32) acc += ba[j] * g_cat[b * 2048 + j];
    for (int o = 16; o; o >>= 1) acc += __shfl_xor_sync(~0u, acc, o);
    if (!lane) g_c[b] = acc;
}

// 6) single-pass flash attention over a 256-seq chunk: 8-row smem subtiles,
//    online softmax; exports raw scores + (m, l, unnormalized ctx) per chunk.
__global__ __launch_bounds__(256) void k_attn(const float* __restrict__ enc) {
    int c = blockIdx.x, b = blockIdx.y;
    __shared__ __align__(16) float srow[8 * 1024];
    __shared__ float ssc[8];
    int tid = threadIdx.x, w = tid >> 5, lane = tid & 31;
    const float4* v4 = reinterpret_cast<const float4*>(g_v + b * 1024);
    float4 vf[8];
#pragma unroll
    for (int j = 0; j < 8; j++) vf[j] = v4[lane + 32 * j];
    float cb = g_c[b];
    float m = -1e30f, l = 0.f;
    float c0 = 0.f, c1 = 0.f, c2 = 0.f, c3 = 0.f;
    const float4* enc4 = reinterpret_cast<const float4*>(enc);
    float4* srow4 = reinterpret_cast<float4*>(srow);
    for (int sub = 0; sub < 32; sub++) {
        int row0 = c * 256 + sub * 8;
        size_t base = ((size_t)b * SEQ + row0 + w) * 256;
        float acc = 0.f;
#pragma unroll
        for (int j = 0; j < 8; j++) {
            float4 e = enc4[base + lane + 32 * j];
            srow4[w * 256 + lane + 32 * j] = e;
            acc += e.x * vf[j].x + e.y * vf[j].y + e.z * vf[j].z + e.w * vf[j].w;
        }
        for (int o = 16; o; o >>= 1) acc += __shfl_xor_sync(~0u, acc, o);
        if (!lane) {
            float s = acc + cb;
            ssc[w] = s;
            g_p[b * SEQ + row0 + w] = s;
        }
        __syncthreads();
        float mloc = ssc[0];
#pragma unroll
        for (int r = 1; r < 8; r++) mloc = fmaxf(mloc, ssc[r]);
        float mnew = fmaxf(m, mloc);
        float f = __expf(m - mnew);
        l *= f; c0 *= f; c1 *= f; c2 *= f; c3 *= f;
#pragma unroll
        for (int r = 0; r < 8; r++) {
            float p = __expf(ssc[r] - mnew);
            l += p;
            c0 += p * srow[r * 1024 + tid];
            c1 += p * srow[r * 1024 + tid + 256];
            c2 += p * srow[r * 1024 + tid + 512];
            c3 += p * srow[r * 1024 + tid + 768];
        }
        m = mnew;
        __syncthreads();
    }
    size_t ci = (size_t)(b * 8 + c) * 1024;
    g_pctx[ci + tid] = c0;       g_pctx[ci + tid + 256] = c1;
    g_pctx[ci + tid + 512] = c2; g_pctx[ci + tid + 768] = c3;
    if (!tid) { g_pm[b * 8 + c] = m; g_pl[b * 8 + c] = l; }
}

// 7) attention combine
__global__ void k_attn_final(float* __restrict__ out_ctx, float* __restrict__ out_attn) {
    int b = blockIdx.x, tid = threadIdx.x;
    float M = g_pm[b * 8];
    for (int cc = 1; cc < 8; cc++) M = fmaxf(M, g_pm[b * 8 + cc]);
    float L = 0.f, f[8];
    for (int cc = 0; cc < 8; cc++) {
        f[cc] = __expf(g_pm[b * 8 + cc] - M);
        L += g_pl[b * 8 + cc] * f[cc];
    }
    float inv = 1.f / L;
    for (int q = 0; q < 4; q++) {
        int h = tid + 256 * q;
        float s = 0.f;
        for (int cc = 0; cc < 8; cc++)
            s += g_pctx[(size_t)(b * 8 + cc) * 1024 + h] * f[cc];
        s *= inv;
        out_ctx[b * 1024 + h] = s;
        g_cat[b * 2048 + 1024 + h] = s;
    }
    for (int s = tid; s < 2048; s += 256)
        out_attn[b * 2048 + s] = __expf(g_p[b * 2048 + s] - M) * inv;
}

// 8) logits combine + softmax
__global__ void k_lcomb(const float* __restrict__ bo, float* __restrict__ out) {
    int idx = blockIdx.x * 256 + threadIdx.x;
    int b = idx / 32000, mm = idx - b * 32000;
    float s = bo[mm];
    for (int z = 0; z < 4; z++)
        s += g_plog[(size_t)z * 1024000 + (size_t)b * 32000 + mm];
    out[idx] = s;
}

__global__ void k_smax1(const float* __restrict__ logits) {
    int b = blockIdx.x, cc = blockIdx.y, tid = threadIdx.x;
    __shared__ float rs[256];
    const float* base = logits + (size_t)b * 32000 + cc * 8000;
    float m = -1e30f;
    for (int i = tid; i < 8000; i += 256) m = fmaxf(m, base[i]);
    rs[tid] = m; __syncthreads();
    for (int o = 128; o; o >>= 1) { if (tid < o) rs[tid] = fmaxf(rs[tid], rs[tid + o]); __syncthreads(); }
    m = rs[0]; __syncthreads();
    float l = 0.f;
    for (int i = tid; i < 8000; i += 256) l += __expf(base[i] - m);
    rs[tid] = l; __syncthreads();
    for (int o = 128; o; o >>= 1) { if (tid < o) rs[tid] += rs[tid + o]; __syncthreads(); }
    if (!tid) { g_lm[b * 4 + cc] = m; g_ll[b * 4 + cc] = rs[0]; }
}

__global__ void k_smax2(float* __restrict__ out) {
    int idx = blockIdx.x * 256 + threadIdx.x;
    int b = idx / 32000;
    float M = g_lm[b * 4];
    for (int cc = 1; cc < 4; cc++) M = fmaxf(M, g_lm[b * 4 + cc]);
    float L = 0.f;
    for (int cc = 0; cc < 4; cc++) L += g_ll[b * 4 + cc] * __expf(g_lm[b * 4 + cc] - M);
    out[idx] = __expf(out[idx] - M) / L;
}

extern "C" void kernel_launch(void* const* d_in, const int* in_sizes, int n_in,
                              void* d_out, int out_size) {
    const int*   ids  = (const int*)d_in[0];
    const float* lctx = (const float*)d_in[1];
    const float* hid  = (const float*)d_in[2];
    const float* enc  = (const float*)d_in[3];
    const float* emb  = (const float*)d_in[4];
    const float* Wat  = (const float*)d_in[5];
    const float* bat  = (const float*)d_in[6];
    const float* Wih0 = (const float*)d_in[7];
    const float* Whh0 = (const float*)d_in[8];
    const float* bih0 = (const float*)d_in[9];
    const float* bhh0 = (const float*)d_in[10];
    const float* Wih1 = (const float*)d_in[11];
    const float* Whh1 = (const float*)d_in[12];
    const float* bih1 = (const float*)d_in[13];
    const float* bhh1 = (const float*)d_in[14];
    const float* Wout = (const float*)d_in[15];
    const float* bout = (const float*)d_in[16];
    float* out    = (float*)d_out;
    float* o_sm   = out;
    float* o_ctx  = out + 1024000;
    float* o_hid  = out + 1024000 + 32768;
    float* o_attn = out + 1024000 + 32768 + 65536;

    k_embed<<<256, 256>>>(ids, lctx, emb);
    k_gemm<<<dim3(24, 8), 256>>>(Wih0, nullptr, 1, 3072, 2048, 8, 0);
    k_gemm<<<dim3(24, 8), 256>>>(Whh0, hid, 0, 3072, 1024, 8, 1);
    k_gru<<<128, 256>>>(bih0, bhh0, hid, 8, 0, o_hid);
    k_gemm<<<dim3(24, 8), 256>>>(Wih1, nullptr, 2, 3072, 1024, 8, 0);
    k_gemm<<<dim3(24, 8), 256>>>(Whh1, hid + 32768, 0, 3072, 1024, 8, 1);
    k_gru<<<128, 256>>>(bih1, bhh1, hid + 32768, 8, 1, o_hid + 32768);
    k_vproj<<<dim3(4, 8), 256>>>(Wat);
    k_vreduce<<<128, 256>>>();
    k_cvec<<<1, 1024>>>(bat);
    k_attn<<<dim3(8, 32), 256>>>(enc);
    k_attn_final<<<32, 256>>>(o_ctx, o_attn);
    k_gemm<<<dim3(250, 4), 256>>>(Wout, nullptr, 3, 32000, 2048, 4, 2);
    k_lcomb<<<4000, 256>>>(bout, o_sm);
    k_smax1<<<dim3(32, 4), 256>>>(o_sm);
    k_smax2<<<4000, 256>>>(o_sm);
}

// round 6
// speedup vs baseline: 1.2162x; 1.1191x over previous
#include <cuda_runtime.h>
#include <math.h>

#define SEQ 2048
#define HID 1024
#define VOC 32000

// ---- static scratch ----
__device__ float g_rnn_in[32 * 2048];
__device__ float g_h0[32 * 1024];
__device__ float g_cat[32 * 2048];          // [h1 | context]
__device__ float g_xt[2048 * 32];           // transposed [k][b] of [h1|context]
__device__ float g_v[32 * 1024];
__device__ float g_vpart[8 * 32 * 1024];
__device__ float g_c[32];
__device__ float g_p[32 * 2048];            // raw scores
__device__ float g_pm[32 * 16];
__device__ float g_pl[32 * 16];
__device__ float g_pctx[32 * 16 * 1024];
__device__ float g_lm[32 * 4];
__device__ float g_ll[32 * 4];
__device__ float g_pi[4 * 32 * 3072];
__device__ float g_ph[4 * 32 * 3072];

// ---- packed f32x2 helpers ----
__device__ __forceinline__ void fma2(unsigned long long& d, unsigned long long a,
                                     unsigned long long x) {
    asm("fma.rn.f32x2 %0, %1, %2, %0;" : "+l"(d) : "l"(a), "l"(x));
}
__device__ __forceinline__ unsigned long long pack2(float a) {
    unsigned long long r;
    asm("mov.b64 %0, {%1, %1};" : "=l"(r) : "f"(a));
    return r;
}
__device__ __forceinline__ void unpack2(unsigned long long v, float& lo, float& hi) {
    asm("mov.b64 {%0, %1}, %2;" : "=f"(lo), "=f"(hi) : "l"(v));
}
// ---- cp.async helpers ----
__device__ __forceinline__ unsigned su32(const void* p) {
    unsigned a;
    asm("{ .reg .u64 t; cvta.to.shared.u64 t, %1; cvt.u32.u64 %0, t; }" : "=r"(a) : "l"(p));
    return a;
}
__device__ __forceinline__ void cp16(unsigned s, const void* g) {
    asm volatile("cp.async.ca.shared.global [%0], [%1], 16;" :: "r"(s), "l"(g));
}
__device__ __forceinline__ void cp_commit() {
    asm volatile("cp.async.commit_group;" ::: "memory");
}
__device__ __forceinline__ void cp_wait1() {
    asm volatile("cp.async.wait_group 1;" ::: "memory");
}
__device__ __forceinline__ void cp_wait0() {
    asm volatile("cp.async.wait_group 0;" ::: "memory");
}

// 1) embedding gather + concat
__global__ void k_embed(const int* __restrict__ ids, const float* __restrict__ lctx,
                        const float* __restrict__ emb) {
    int idx = blockIdx.x * 256 + threadIdx.x;
    int b = idx >> 11, j = idx & 2047;
    g_rnn_in[idx] = (j < HID) ? emb[(size_t)ids[b] * HID + j]
                              : lctx[b * HID + (j - HID)];
}

// 2) k-split GEMM for GRU gates (f32x2)
__global__ __launch_bounds__(256) void k_gemm(const float* __restrict__ A,
        const float* __restrict__ Xext, int xsel, int M, int K, int ks, int dsel) {
    const float* X = (xsel == 0) ? Xext : (xsel == 1) ? g_rnn_in : g_h0;
    float* P = (dsel == 0) ? g_pi : g_ph;
    int z = blockIdx.y;
    int kc = K / ks, kb = z * kc;
    __shared__ __align__(16) float As[128 * 36];
    __shared__ __align__(16) float Xs[32 * 36];
    int tid = threadIdx.x;
    int tx = tid & 7, ty = tid >> 3;
    int mb = blockIdx.x * 128;
    unsigned long long acc[4][2];
#pragma unroll
    for (int jj = 0; jj < 4; jj++) { acc[jj][0] = 0ull; acc[jj][1] = 0ull; }
    for (int k0 = kb; k0 < kb + kc; k0 += 32) {
#pragma unroll
        for (int l = 0; l < 4; l++) {
            int idx = tid + 256 * l;
            int row = idx >> 3, q = idx & 7;
            float4 v = *reinterpret_cast<const float4*>(
                &A[(size_t)(mb + row) * K + k0 + q * 4]);
            *reinterpret_cast<float4*>(&As[row * 36 + q * 4]) = v;
        }
#pragma unroll
        for (int l = 0; l < 4; l++) {
            int idx = tid + 256 * l;
            int b = idx >> 5, kk = idx & 31;
            Xs[kk * 36 + b] = X[(size_t)b * K + k0 + kk];
        }
        __syncthreads();
#pragma unroll
        for (int kk = 0; kk < 32; kk++) {
            unsigned long long x01 =
                *reinterpret_cast<const unsigned long long*>(&Xs[kk * 36 + tx * 4]);
            unsigned long long x23 =
                *reinterpret_cast<const unsigned long long*>(&Xs[kk * 36 + tx * 4 + 2]);
#pragma unroll
            for (int jj = 0; jj < 4; jj++) {
                unsigned long long a2 = pack2(As[(ty + 32 * jj) * 36 + kk]);
                fma2(acc[jj][0], a2, x01);
                fma2(acc[jj][1], a2, x23);
            }
        }
        __syncthreads();
    }
    float* Pz = P + (size_t)z * 32 * M;
#pragma unroll
    for (int jj = 0; jj < 4; jj++) {
        int row = mb + ty + 32 * jj;
        float v0, v1, v2, v3;
        unpack2(acc[jj][0], v0, v1);
        unpack2(acc[jj][1], v2, v3);
        Pz[(size_t)(tx * 4 + 0) * M + row] = v0;
        Pz[(size_t)(tx * 4 + 1) * M + row] = v1;
        Pz[(size_t)(tx * 4 + 2) * M + row] = v2;
        Pz[(size_t)(tx * 4 + 3) * M + row] = v3;
    }
}

// 3) GRU combine (ks=4); layer1 also writes transposed g_xt
__global__ void k_gru(const float* __restrict__ bih, const float* __restrict__ bhh,
                      const float* __restrict__ hprev, int ks, int layer,
                      float* __restrict__ dout) {
    int idx = blockIdx.x * 256 + threadIdx.x;
    int b = idx >> 10, h = idx & 1023;
    const int M = 3072;
    float ir = bih[h], iz = bih[1024 + h], in = bih[2048 + h];
    float hr = bhh[h], hz = bhh[1024 + h], hn = bhh[2048 + h];
    for (int z = 0; z < ks; z++) {
        const float* pi = g_pi + (size_t)z * 32 * M + (size_t)b * M;
        const float* ph = g_ph + (size_t)z * 32 * M + (size_t)b * M;
        ir += pi[h]; iz += pi[1024 + h]; in += pi[2048 + h];
        hr += ph[h]; hz += ph[1024 + h]; hn += ph[2048 + h];
    }
    float r = 1.f / (1.f + __expf(-(ir + hr)));
    float zz = 1.f / (1.f + __expf(-(iz + hz)));
    float n = tanhf(in + r * hn);
    float outv = (1.f - zz) * n + zz * hprev[b * 1024 + h];
    if (layer == 0) g_h0[idx] = outv;
    else { g_cat[b * 2048 + h] = outv; g_xt[h * 32 + b] = outv; }
    dout[b * 1024 + h] = outv;
}

// 4) v = h1 @ W_attn (j-chunked, f32x2)
__global__ __launch_bounds__(256) void k_vproj(const float* __restrict__ W) {
    __shared__ __align__(16) float xs[128 * 34];
    int tid = threadIdx.x;
    int jc = blockIdx.y;
    for (int l = 0; l < 16; l++) {
        int idx = tid + 256 * l;
        int j = idx >> 5, b = idx & 31;
        xs[j * 34 + b] = g_cat[b * 2048 + jc * 128 + j];
    }
    __syncthreads();
    int k = blockIdx.x * 256 + tid;
    unsigned long long acc[16];
#pragma unroll
    for (int p = 0; p < 16; p++) acc[p] = 0ull;
    for (int j = 0; j < 128; j++) {
        unsigned long long w2 = pack2(W[(size_t)(jc * 128 + j) * 1024 + k]);
#pragma unroll
        for (int p = 0; p < 16; p++)
            fma2(acc[p], w2,
                 *reinterpret_cast<const unsigned long long*>(&xs[j * 34 + 2 * p]));
    }
#pragma unroll
    for (int p = 0; p < 16; p++) {
        float lo, hi;
        unpack2(acc[p], lo, hi);
        g_vpart[(size_t)jc * 32768 + (2 * p) * 1024 + k] = lo;
        g_vpart[(size_t)jc * 32768 + (2 * p + 1) * 1024 + k] = hi;
    }
}

// 5) v-reduce + cvec merged (block 128 does cvec)
__global__ void k_vreduce(const float* __restrict__ ba) {
    if (blockIdx.x == 128) {
        int w = threadIdx.x >> 5, lane = threadIdx.x & 31;
        for (int bq = 0; bq < 4; bq++) {
            int b = w * 4 + bq;
            float acc = 0.f;
            for (int j = lane; j < 1024; j += 32) acc += ba[j] * g_cat[b * 2048 + j];
            for (int o = 16; o; o >>= 1) acc += __shfl_xor_sync(~0u, acc, o);
            if (!lane) g_c[b] = acc;
        }
        return;
    }
    int idx = blockIdx.x * 256 + threadIdx.x;
    float s = 0.f;
    for (int jc = 0; jc < 8; jc++) s += g_vpart[(size_t)jc * 32768 + idx];
    g_v[idx] = s;
}

// 6) flash attention, 16 chunks of 128 rows, register prefetch of next 8-row tile
__global__ __launch_bounds__(256) void k_attn(const float* __restrict__ enc) {
    int c = blockIdx.x, b = blockIdx.y;
    __shared__ __align__(16) float srow[8 * 1024];
    __shared__ float ssc[8];
    int tid = threadIdx.x, w = tid >> 5, lane = tid & 31;
    const float4* v4 = reinterpret_cast<const float4*>(g_v + b * 1024);
    float4 vf[8];
#pragma unroll
    for (int j = 0; j < 8; j++) vf[j] = v4[lane + 32 * j];
    float cb = g_c[b];
    float m = -1e30f, l = 0.f;
    float c0 = 0.f, c1 = 0.f, c2 = 0.f, c3 = 0.f;
    const float4* enc4 = reinterpret_cast<const float4*>(enc);
    float4* srow4 = reinterpret_cast<float4*>(srow);
    float4 e[8];
    {
        size_t base = ((size_t)b * SEQ + c * 128 + w) * 256;
#pragma unroll
        for (int j = 0; j < 8; j++) e[j] = enc4[base + lane + 32 * j];
    }
    for (int sub = 0; sub < 16; sub++) {
        int row0 = c * 128 + sub * 8;
        float acc = 0.f;
#pragma unroll
        for (int j = 0; j < 8; j++) {
            srow4[w * 256 + lane + 32 * j] = e[j];
            acc += e[j].x * vf[j].x + e[j].y * vf[j].y + e[j].z * vf[j].z + e[j].w * vf[j].w;
        }
        for (int o = 16; o; o >>= 1) acc += __shfl_xor_sync(~0u, acc, o);
        if (!lane) {
            float s = acc + cb;
            ssc[w] = s;
            g_p[b * SEQ + row0 + w] = s;
        }
        __syncthreads();
        if (sub < 15) {
            size_t nb = ((size_t)b * SEQ + row0 + 8 + w) * 256;
#pragma unroll
            for (int j = 0; j < 8; j++) e[j] = enc4[nb + lane + 32 * j];
        }
        float mloc = ssc[0];
#pragma unroll
        for (int r = 1; r < 8; r++) mloc = fmaxf(mloc, ssc[r]);
        float mnew = fmaxf(m, mloc);
        float f = __expf(m - mnew);
        l *= f; c0 *= f; c1 *= f; c2 *= f; c3 *= f;
#pragma unroll
        for (int r = 0; r < 8; r++) {
            float p = __expf(ssc[r] - mnew);
            l += p;
            c0 += p * srow[r * 1024 + tid];
            c1 += p * srow[r * 1024 + tid + 256];
            c2 += p * srow[r * 1024 + tid + 512];
            c3 += p * srow[r * 1024 + tid + 768];
        }
        m = mnew;
        __syncthreads();
    }
    size_t ci = (size_t)(b * 16 + c) * 1024;
    g_pctx[ci + tid] = c0;       g_pctx[ci + tid + 256] = c1;
    g_pctx[ci + tid + 512] = c2; g_pctx[ci + tid + 768] = c3;
    if (!tid) { g_pm[b * 16 + c] = m; g_pl[b * 16 + c] = l; }
}

// 7) attention combine: context (+g_xt transposed) + normalized weights
__global__ void k_attn_final(float* __restrict__ out_ctx, float* __restrict__ out_attn) {
    int b = blockIdx.x, tid = threadIdx.x;
    float M = g_pm[b * 16];
    for (int cc = 1; cc < 16; cc++) M = fmaxf(M, g_pm[b * 16 + cc]);
    float L = 0.f, f[16];
    for (int cc = 0; cc < 16; cc++) {
        f[cc] = __expf(g_pm[b * 16 + cc] - M);
        L += g_pl[b * 16 + cc] * f[cc];
    }
    float inv = 1.f / L;
    for (int q = 0; q < 4; q++) {
        int h = tid + 256 * q;
        float s = 0.f;
        for (int cc = 0; cc < 16; cc++)
            s += g_pctx[(size_t)(b * 16 + cc) * 1024 + h] * f[cc];
        s *= inv;
        out_ctx[b * 1024 + h] = s;
        g_xt[(1024 + h) * 32 + b] = s;
    }
    for (int s = tid; s < 2048; s += 256)
        out_attn[b * 2048 + s] = __expf(g_p[b * 2048 + s] - M) * inv;
}

// 8) logits GEMM: full K per block, cp.async double-buffered, bias fused
__global__ __launch_bounds__(256) void k_logits(const float* __restrict__ Wout,
                                                const float* __restrict__ bout,
                                                float* __restrict__ out) {
    __shared__ __align__(16) float As[2][128 * 36];
    __shared__ __align__(16) float Xs[2][32 * 36];
    int tid = threadIdx.x;
    int tx = tid & 7, ty = tid >> 3;
    int mb = blockIdx.x * 128;
    unsigned long long acc[4][2];
#pragma unroll
    for (int jj = 0; jj < 4; jj++) { acc[jj][0] = 0ull; acc[jj][1] = 0ull; }

    // prologue: A tile 128 rows x 32 floats = 1024 cp16 chunks (4 loops x 256 thr)
    {
#pragma unroll
        for (int l = 0; l < 4; l++) {
            int idx = tid + 256 * l;
            int row = idx >> 3, q = idx & 7;
            cp16(su32(&As[0][row * 36 + q * 4]),
                 &Wout[(size_t)(mb + row) * 2048 + q * 4]);
        }
        int kk = tid >> 3, q = tid & 7;
        cp16(su32(&Xs[0][kk * 36 + q * 4]), &g_xt[kk * 32 + q * 4]);
        cp_commit();
    }
    for (int j = 0; j < 64; j++) {
        int cur = j & 1;
        if (j + 1 < 64) {
            int nb = 1 - cur;
#pragma unroll
            for (int l = 0; l < 4; l++) {
                int idx = tid + 256 * l;
                int row = idx >> 3, q = idx & 7;
                cp16(su32(&As[nb][row * 36 + q * 4]),
                     &Wout[(size_t)(mb + row) * 2048 + (j + 1) * 32 + q * 4]);
            }
            int kk = tid >> 3, q = tid & 7;
            cp16(su32(&Xs[nb][kk * 36 + q * 4]),
                 &g_xt[((j + 1) * 32 + kk) * 32 + q * 4]);
            cp_commit();
            cp_wait1();
        } else {
            cp_wait0();
        }
        __syncthreads();
#pragma unroll
        for (int kk = 0; kk < 32; kk++) {
            unsigned long long x01 =
                *reinterpret_cast<const unsigned long long*>(&Xs[cur][kk * 36 + tx * 4]);
            unsigned long long x23 =
                *reinterpret_cast<const unsigned long long*>(&Xs[cur][kk * 36 + tx * 4 + 2]);
#pragma unroll
            for (int jj = 0; jj < 4; jj++) {
                unsigned long long a2 = pack2(As[cur][(ty + 32 * jj) * 36 + kk]);
                fma2(acc[jj][0], a2, x01);
                fma2(acc[jj][1], a2, x23);
            }
        }
        __syncthreads();
    }
#pragma unroll
    for (int jj = 0; jj < 4; jj++) {
        int row = mb + ty + 32 * jj;
        float bias = bout[row];
        float v0, v1, v2, v3;
        unpack2(acc[jj][0], v0, v1);
        unpack2(acc[jj][1], v2, v3);
        out[(size_t)(tx * 4 + 0) * VOC + row] = v0 + bias;
        out[(size_t)(tx * 4 + 1) * VOC + row] = v1 + bias;
        out[(size_t)(tx * 4 + 2) * VOC + row] = v2 + bias;
        out[(size_t)(tx * 4 + 3) * VOC + row] = v3 + bias;
    }
}

// 9) softmax over vocab (chunked)
__global__ void k_smax1(const float* __restrict__ logits) {
    int b = blockIdx.x, cc = blockIdx.y, tid = threadIdx.x;
    __shared__ float rs[256];
    const float* base = logits + (size_t)b * 32000 + cc * 8000;
    float m = -1e30f;
    for (int i = tid; i < 8000; i += 256) m = fmaxf(m, base[i]);
    rs[tid] = m; __syncthreads();
    for (int o = 128; o; o >>= 1) { if (tid < o) rs[tid] = fmaxf(rs[tid], rs[tid + o]); __syncthreads(); }
    m = rs[0]; __syncthreads();
    float l = 0.f;
    for (int i = tid; i < 8000; i += 256) l += __expf(base[i] - m);
    rs[tid] = l; __syncthreads();
    for (int o = 128; o; o >>= 1) { if (tid < o) rs[tid] += rs[tid + o]; __syncthreads(); }
    if (!tid) { g_lm[b * 4 + cc] = m; g_ll[b * 4 + cc] = rs[0]; }
}

__global__ void k_smax2(float* __restrict__ out) {
    int idx = blockIdx.x * 256 + threadIdx.x;
    int b = idx / 32000;
    float M = g_lm[b * 4];
    for (int cc = 1; cc < 4; cc++) M = fmaxf(M, g_lm[b * 4 + cc]);
    float L = 0.f;
    for (int cc = 0; cc < 4; cc++) L += g_ll[b * 4 + cc] * __expf(g_lm[b * 4 + cc] - M);
    out[idx] = __expf(out[idx] - M) / L;
}

extern "C" void kernel_launch(void* const* d_in, const int* in_sizes, int n_in,
                              void* d_out, int out_size) {
    const int*   ids  = (const int*)d_in[0];
    const float* lctx = (const float*)d_in[1];
    const float* hid  = (const float*)d_in[2];
    const float* enc  = (const float*)d_in[3];
    const float* emb  = (const float*)d_in[4];
    const float* Wat  = (const float*)d_in[5];
    const float* bat  = (const float*)d_in[6];
    const float* Wih0 = (const float*)d_in[7];
    const float* Whh0 = (const float*)d_in[8];
    const float* bih0 = (const float*)d_in[9];
    const float* bhh0 = (const float*)d_in[10];
    const float* Wih1 = (const float*)d_in[11];
    const float* Whh1 = (const float*)d_in[12];
    const float* bih1 = (const float*)d_in[13];
    const float* bhh1 = (const float*)d_in[14];
    const float* Wout = (const float*)d_in[15];
    const float* bout = (const float*)d_in[16];
    float* out    = (float*)d_out;
    float* o_sm   = out;
    float* o_ctx  = out + 1024000;
    float* o_hid  = out + 1024000 + 32768;
    float* o_attn = out + 1024000 + 32768 + 65536;

    k_embed<<<256, 256>>>(ids, lctx, emb);
    k_gemm<<<dim3(24, 4), 256>>>(Wih0, nullptr, 1, 3072, 2048, 4, 0);
    k_gemm<<<dim3(24, 4), 256>>>(Whh0, hid, 0, 3072, 1024, 4, 1);
    k_gru<<<128, 256>>>(bih0, bhh0, hid, 4, 0, o_hid);
    k_gemm<<<dim3(24, 4), 256>>>(Wih1, nullptr, 2, 3072, 1024, 4, 0);
    k_gemm<<<dim3(24, 4), 256>>>(Whh1, hid + 32768, 0, 3072, 1024, 4, 1);
    k_gru<<<128, 256>>>(bih1, bhh1, hid + 32768, 4, 1, o_hid + 32768);
    k_vproj<<<dim3(4, 8), 256>>>(Wat);
    k_vreduce<<<129, 256>>>(bat);
    k_attn<<<dim3(16, 32), 256>>>(enc);
    k_attn_final<<<32, 256>>>(o_ctx, o_attn);
    k_logits<<<250, 256>>>(Wout, bout, o_sm);
    k_smax1<<<dim3(32, 4), 256>>>(o_sm);
    k_smax2<<<4000, 256>>>(o_sm);
}

// round 7
// speedup vs baseline: 1.2915x; 1.0619x over previous
#include <cuda_runtime.h>
#include <math.h>

#define SEQ 2048
#define HID 1024
#define VOC 32000

// ---- static scratch ----
__device__ float g_rnn_in[32 * 2048];
__device__ float g_h0[32 * 1024];
__device__ float g_cat[32 * 2048];          // [h1 | context]
__device__ float g_xt[2048 * 32];           // transposed [k][b] of [h1|context]
__device__ float g_v[32 * 1024];
__device__ float g_vpart[8 * 32 * 1024];
__device__ float g_c[32];
__device__ float g_p[32 * 2048];            // raw scores
__device__ float g_pm[32 * 16];
__device__ float g_pl[32 * 16];
__device__ float g_pctx[32 * 16 * 1024];
__device__ float g_lm[32 * 4];
__device__ float g_ll[32 * 4];
__device__ float g_pi[4 * 32 * 3072];
__device__ float g_ph[4 * 32 * 3072];

// ---- packed f32x2 helpers ----
__device__ __forceinline__ void fma2(unsigned long long& d, unsigned long long a,
                                     unsigned long long x) {
    asm("fma.rn.f32x2 %0, %1, %2, %0;" : "+l"(d) : "l"(a), "l"(x));
}
__device__ __forceinline__ unsigned long long pack2(float a) {
    unsigned long long r;
    asm("mov.b64 %0, {%1, %1};" : "=l"(r) : "f"(a));
    return r;
}
__device__ __forceinline__ void unpack2(unsigned long long v, float& lo, float& hi) {
    asm("mov.b64 {%0, %1}, %2;" : "=f"(lo), "=f"(hi) : "l"(v));
}
// ---- cp.async helpers ----
__device__ __forceinline__ unsigned su32(const void* p) {
    unsigned a;
    asm("{ .reg .u64 t; cvta.to.shared.u64 t, %1; cvt.u32.u64 %0, t; }" : "=r"(a) : "l"(p));
    return a;
}
__device__ __forceinline__ void cp16(unsigned s, const void* g) {
    asm volatile("cp.async.ca.shared.global [%0], [%1], 16;" :: "r"(s), "l"(g));
}
__device__ __forceinline__ void cp_commit() {
    asm volatile("cp.async.commit_group;" ::: "memory");
}
__device__ __forceinline__ void cp_wait1() {
    asm volatile("cp.async.wait_group 1;" ::: "memory");
}
__device__ __forceinline__ void cp_wait0() {
    asm volatile("cp.async.wait_group 0;" ::: "memory");
}

// 1) embedding gather + concat
__global__ void k_embed(const int* __restrict__ ids, const float* __restrict__ lctx,
                        const float* __restrict__ emb) {
    int idx = blockIdx.x * 256 + threadIdx.x;
    int b = idx >> 11, j = idx & 2047;
    g_rnn_in[idx] = (j < HID) ? emb[(size_t)ids[b] * HID + j]
                              : lctx[b * HID + (j - HID)];
}

// 2) dual k-split GEMM for one GRU layer: z=0 -> gi (A0), z=1 -> gh (A1)
__global__ __launch_bounds__(256) void k_gemm2(const float* __restrict__ A0,
        const float* __restrict__ A1, const float* __restrict__ X1,
        int xsel0, int K0, int K1) {
    int zz2 = blockIdx.z;
    const float* A = zz2 ? A1 : A0;
    const float* X = zz2 ? X1 : ((xsel0 == 1) ? g_rnn_in : g_h0);
    int K = zz2 ? K1 : K0;
    float* P = zz2 ? g_ph : g_pi;
    const int M = 3072;
    int z = blockIdx.y;
    int kc = K / 4, kb = z * kc;
    __shared__ __align__(16) float As[128 * 36];
    __shared__ __align__(16) float Xs[32 * 36];
    int tid = threadIdx.x;
    int tx = tid & 7, ty = tid >> 3;
    int mb = blockIdx.x * 128;
    unsigned long long acc[4][2];
#pragma unroll
    for (int jj = 0; jj < 4; jj++) { acc[jj][0] = 0ull; acc[jj][1] = 0ull; }
    for (int k0 = kb; k0 < kb + kc; k0 += 32) {
#pragma unroll
        for (int l = 0; l < 4; l++) {
            int idx = tid + 256 * l;
            int row = idx >> 3, q = idx & 7;
            float4 v = *reinterpret_cast<const float4*>(
                &A[(size_t)(mb + row) * K + k0 + q * 4]);
            *reinterpret_cast<float4*>(&As[row * 36 + q * 4]) = v;
        }
#pragma unroll
        for (int l = 0; l < 4; l++) {
            int idx = tid + 256 * l;
            int b = idx >> 5, kk = idx & 31;
            Xs[kk * 36 + b] = X[(size_t)b * K + k0 + kk];
        }
        __syncthreads();
#pragma unroll
        for (int kk = 0; kk < 32; kk++) {
            unsigned long long x01 =
                *reinterpret_cast<const unsigned long long*>(&Xs[kk * 36 + tx * 4]);
            unsigned long long x23 =
                *reinterpret_cast<const unsigned long long*>(&Xs[kk * 36 + tx * 4 + 2]);
#pragma unroll
            for (int jj = 0; jj < 4; jj++) {
                unsigned long long a2 = pack2(As[(ty + 32 * jj) * 36 + kk]);
                fma2(acc[jj][0], a2, x01);
                fma2(acc[jj][1], a2, x23);
            }
        }
        __syncthreads();
    }
    float* Pz = P + (size_t)z * 32 * M;
#pragma unroll
    for (int jj = 0; jj < 4; jj++) {
        int row = mb + ty + 32 * jj;
        float v0, v1, v2, v3;
        unpack2(acc[jj][0], v0, v1);
        unpack2(acc[jj][1], v2, v3);
        Pz[(size_t)(tx * 4 + 0) * M + row] = v0;
        Pz[(size_t)(tx * 4 + 1) * M + row] = v1;
        Pz[(size_t)(tx * 4 + 2) * M + row] = v2;
        Pz[(size_t)(tx * 4 + 3) * M + row] = v3;
    }
}

// 3) GRU combine (ks=4); layer1 also writes transposed g_xt
__global__ void k_gru(const float* __restrict__ bih, const float* __restrict__ bhh,
                      const float* __restrict__ hprev, int ks, int layer,
                      float* __restrict__ dout) {
    int idx = blockIdx.x * 256 + threadIdx.x;
    int b = idx >> 10, h = idx & 1023;
    const int M = 3072;
    float ir = bih[h], iz = bih[1024 + h], in = bih[2048 + h];
    float hr = bhh[h], hz = bhh[1024 + h], hn = bhh[2048 + h];
    for (int z = 0; z < ks; z++) {
        const float* pi = g_pi + (size_t)z * 32 * M + (size_t)b * M;
        const float* ph = g_ph + (size_t)z * 32 * M + (size_t)b * M;
        ir += pi[h]; iz += pi[1024 + h]; in += pi[2048 + h];
        hr += ph[h]; hz += ph[1024 + h]; hn += ph[2048 + h];
    }
    float r = 1.f / (1.f + __expf(-(ir + hr)));
    float zz = 1.f / (1.f + __expf(-(iz + hz)));
    float n = tanhf(in + r * hn);
    float outv = (1.f - zz) * n + zz * hprev[b * 1024 + h];
    if (layer == 0) g_h0[idx] = outv;
    else { g_cat[b * 2048 + h] = outv; g_xt[h * 32 + b] = outv; }
    dout[b * 1024 + h] = outv;
}

// 4) v = h1 @ W_attn (j-chunked, f32x2)
__global__ __launch_bounds__(256) void k_vproj(const float* __restrict__ W) {
    __shared__ __align__(16) float xs[128 * 34];
    int tid = threadIdx.x;
    int jc = blockIdx.y;
    for (int l = 0; l < 16; l++) {
        int idx = tid + 256 * l;
        int j = idx >> 5, b = idx & 31;
        xs[j * 34 + b] = g_cat[b * 2048 + jc * 128 + j];
    }
    __syncthreads();
    int k = blockIdx.x * 256 + tid;
    unsigned long long acc[16];
#pragma unroll
    for (int p = 0; p < 16; p++) acc[p] = 0ull;
    for (int j = 0; j < 128; j++) {
        unsigned long long w2 = pack2(W[(size_t)(jc * 128 + j) * 1024 + k]);
#pragma unroll
        for (int p = 0; p < 16; p++)
            fma2(acc[p], w2,
                 *reinterpret_cast<const unsigned long long*>(&xs[j * 34 + 2 * p]));
    }
#pragma unroll
    for (int p = 0; p < 16; p++) {
        float lo, hi;
        unpack2(acc[p], lo, hi);
        g_vpart[(size_t)jc * 32768 + (2 * p) * 1024 + k] = lo;
        g_vpart[(size_t)jc * 32768 + (2 * p + 1) * 1024 + k] = hi;
    }
}

// 5) v-reduce + cvec merged (block 128 does cvec)
__global__ void k_vreduce(const float* __restrict__ ba) {
    if (blockIdx.x == 128) {
        int w = threadIdx.x >> 5, lane = threadIdx.x & 31;
        for (int bq = 0; bq < 4; bq++) {
            int b = w * 4 + bq;
            float acc = 0.f;
            for (int j = lane; j < 1024; j += 32) acc += ba[j] * g_cat[b * 2048 + j];
            for (int o = 16; o; o >>= 1) acc += __shfl_xor_sync(~0u, acc, o);
            if (!lane) g_c[b] = acc;
        }
        return;
    }
    int idx = blockIdx.x * 256 + threadIdx.x;
    float s = 0.f;
    for (int jc = 0; jc < 8; jc++) s += g_vpart[(size_t)jc * 32768 + idx];
    g_v[idx] = s;
}

// ---- logits GEMM body over K tiles [j0, j1); acc_mode: add previous out ----
__device__ __forceinline__ void logits_body(float* sbuf,
        const float* __restrict__ Wout, const float* __restrict__ bout,
        float* __restrict__ out, int mb, int j0, int j1, bool acc_mode) {
    float* As = sbuf;               // 2 x 128*36 = 9216 floats
    float* Xs = sbuf + 9216;        // 2 x 32*36  = 2304 floats
    int tid = threadIdx.x;
    int tx = tid & 7, ty = tid >> 3;
    unsigned long long acc[4][2];
#pragma unroll
    for (int jj = 0; jj < 4; jj++) { acc[jj][0] = 0ull; acc[jj][1] = 0ull; }
    // prologue
    {
#pragma unroll
        for (int l = 0; l < 4; l++) {
            int idx = tid + 256 * l;
            int row = idx >> 3, q = idx & 7;
            cp16(su32(&As[row * 36 + q * 4]),
                 &Wout[(size_t)(mb + row) * 2048 + j0 * 32 + q * 4]);
        }
        int kk = tid >> 3, q = tid & 7;
        cp16(su32(&Xs[kk * 36 + q * 4]), &g_xt[(j0 * 32 + kk) * 32 + q * 4]);
        cp_commit();
    }
    for (int j = j0; j < j1; j++) {
        int cur = (j - j0) & 1;
        if (j + 1 < j1) {
            int nb = 1 - cur;
#pragma unroll
            for (int l = 0; l < 4; l++) {
                int idx = tid + 256 * l;
                int row = idx >> 3, q = idx & 7;
                cp16(su32(&As[nb * 4608 + row * 36 + q * 4]),
                     &Wout[(size_t)(mb + row) * 2048 + (j + 1) * 32 + q * 4]);
            }
            int kk = tid >> 3, q = tid & 7;
            cp16(su32(&Xs[nb * 1152 + kk * 36 + q * 4]),
                 &g_xt[((j + 1) * 32 + kk) * 32 + q * 4]);
            cp_commit();
            cp_wait1();
        } else {
            cp_wait0();
        }
        __syncthreads();
#pragma unroll
        for (int kk = 0; kk < 32; kk++) {
            unsigned long long x01 = *reinterpret_cast<const unsigned long long*>(
                &Xs[cur * 1152 + kk * 36 + tx * 4]);
            unsigned long long x23 = *reinterpret_cast<const unsigned long long*>(
                &Xs[cur * 1152 + kk * 36 + tx * 4 + 2]);
#pragma unroll
            for (int jj = 0; jj < 4; jj++) {
                unsigned long long a2 = pack2(As[cur * 4608 + (ty + 32 * jj) * 36 + kk]);
                fma2(acc[jj][0], a2, x01);
                fma2(acc[jj][1], a2, x23);
            }
        }
        __syncthreads();
    }
#pragma unroll
    for (int jj = 0; jj < 4; jj++) {
        int row = mb + ty + 32 * jj;
        float v0, v1, v2, v3;
        unpack2(acc[jj][0], v0, v1);
        unpack2(acc[jj][1], v2, v3);
        if (acc_mode) {
            out[(size_t)(tx * 4 + 0) * VOC + row] += v0;
            out[(size_t)(tx * 4 + 1) * VOC + row] += v1;
            out[(size_t)(tx * 4 + 2) * VOC + row] += v2;
            out[(size_t)(tx * 4 + 3) * VOC + row] += v3;
        } else {
            float bias = bout[row];
            out[(size_t)(tx * 4 + 0) * VOC + row] = v0 + bias;
            out[(size_t)(tx * 4 + 1) * VOC + row] = v1 + bias;
            out[(size_t)(tx * 4 + 2) * VOC + row] = v2 + bias;
            out[(size_t)(tx * 4 + 3) * VOC + row] = v3 + bias;
        }
    }
}

// 6) fused: blocks 0..511 flash attention; blocks 512..761 logits h1-half
__global__ __launch_bounds__(256) void k_attn_logits(const float* __restrict__ enc,
        const float* __restrict__ Wout, const float* __restrict__ bout,
        float* __restrict__ out_sm) {
    __shared__ __align__(16) float sbuf[11520];
    __shared__ float ssc[8];
    int bid = blockIdx.x;
    if (bid >= 512) {
        logits_body(sbuf, Wout, bout, out_sm, (bid - 512) * 128, 0, 32, false);
        return;
    }
    int c = bid & 15, b = bid >> 4;
    float* srow = sbuf;
    int tid = threadIdx.x, w = tid >> 5, lane = tid & 31;
    const float4* v4 = reinterpret_cast<const float4*>(g_v + b * 1024);
    float4 vf[8];
#pragma unroll
    for (int j = 0; j < 8; j++) vf[j] = v4[lane + 32 * j];
    float cb = g_c[b];
    float m = -1e30f, l = 0.f;
    float c0 = 0.f, c1 = 0.f, c2 = 0.f, c3 = 0.f;
    const float4* enc4 = reinterpret_cast<const float4*>(enc);
    float4* srow4 = reinterpret_cast<float4*>(srow);
    float4 e[8];
    {
        size_t base = ((size_t)b * SEQ + c * 128 + w) * 256;
#pragma unroll
        for (int j = 0; j < 8; j++) e[j] = enc4[base + lane + 32 * j];
    }
    for (int sub = 0; sub < 16; sub++) {
        int row0 = c * 128 + sub * 8;
        float acc = 0.f;
#pragma unroll
        for (int j = 0; j < 8; j++) {
            srow4[w * 256 + lane + 32 * j] = e[j];
            acc += e[j].x * vf[j].x + e[j].y * vf[j].y + e[j].z * vf[j].z + e[j].w * vf[j].w;
        }
        for (int o = 16; o; o >>= 1) acc += __shfl_xor_sync(~0u, acc, o);
        if (!lane) {
            float s = acc + cb;
            ssc[w] = s;
            g_p[b * SEQ + row0 + w] = s;
        }
        __syncthreads();
        if (sub < 15) {
            size_t nb = ((size_t)b * SEQ + row0 + 8 + w) * 256;
#pragma unroll
            for (int j = 0; j < 8; j++) e[j] = enc4[nb + lane + 32 * j];
        }
        float mloc = ssc[0];
#pragma unroll
        for (int r = 1; r < 8; r++) mloc = fmaxf(mloc, ssc[r]);
        float mnew = fmaxf(m, mloc);
        float f = __expf(m - mnew);
        l *= f; c0 *= f; c1 *= f; c2 *= f; c3 *= f;
#pragma unroll
        for (int r = 0; r < 8; r++) {
            float p = __expf(ssc[r] - mnew);
            l += p;
            c0 += p * srow[r * 1024 + tid];
            c1 += p * srow[r * 1024 + tid + 256];
            c2 += p * srow[r * 1024 + tid + 512];
            c3 += p * srow[r * 1024 + tid + 768];
        }
        m = mnew;
        __syncthreads();
    }
    size_t ci = (size_t)(b * 16 + c) * 1024;
    g_pctx[ci + tid] = c0;       g_pctx[ci + tid + 256] = c1;
    g_pctx[ci + tid + 512] = c2; g_pctx[ci + tid + 768] = c3;
    if (!tid) { g_pm[b * 16 + c] = m; g_pl[b * 16 + c] = l; }
}

// 7) attention combine: context (+g_xt transposed) + normalized weights
__global__ void k_attn_final(float* __restrict__ out_ctx, float* __restrict__ out_attn) {
    int b = blockIdx.x, tid = threadIdx.x;
    float M = g_pm[b * 16];
    for (int cc = 1; cc < 16; cc++) M = fmaxf(M, g_pm[b * 16 + cc]);
    float L = 0.f, f[16];
    for (int cc = 0; cc < 16; cc++) {
        f[cc] = __expf(g_pm[b * 16 + cc] - M);
        L += g_pl[b * 16 + cc] * f[cc];
    }
    float inv = 1.f / L;
    for (int q = 0; q < 4; q++) {
        int h = tid + 256 * q;
        float s = 0.f;
        for (int cc = 0; cc < 16; cc++)
            s += g_pctx[(size_t)(b * 16 + cc) * 1024 + h] * f[cc];
        s *= inv;
        out_ctx[b * 1024 + h] = s;
        g_xt[(1024 + h) * 32 + b] = s;
    }
    for (int s = tid; s < 2048; s += 256)
        out_attn[b * 2048 + s] = __expf(g_p[b * 2048 + s] - M) * inv;
}

// 8) logits phase 2: context half, accumulate into out
__global__ __launch_bounds__(256) void k_logits2(const float* __restrict__ Wout,
        const float* __restrict__ bout, float* __restrict__ out) {
    __shared__ __align__(16) float sbuf[11520];
    logits_body(sbuf, Wout, bout, out, blockIdx.x * 128, 32, 64, true);
}

// 9) softmax over vocab (chunked)
__global__ void k_smax1(const float* __restrict__ logits) {
    int b = blockIdx.x, cc = blockIdx.y, tid = threadIdx.x;
    __shared__ float rs[256];
    const float* base = logits + (size_t)b * 32000 + cc * 8000;
    float m = -1e30f;
    for (int i = tid; i < 8000; i += 256) m = fmaxf(m, base[i]);
    rs[tid] = m; __syncthreads();
    for (int o = 128; o; o >>= 1) { if (tid < o) rs[tid] = fmaxf(rs[tid], rs[tid + o]); __syncthreads(); }
    m = rs[0]; __syncthreads();
    float l = 0.f;
    for (int i = tid; i < 8000; i += 256) l += __expf(base[i] - m);
    rs[tid] = l; __syncthreads();
    for (int o = 128; o; o >>= 1) { if (tid < o) rs[tid] += rs[tid + o]; __syncthreads(); }
    if (!tid) { g_lm[b * 4 + cc] = m; g_ll[b * 4 + cc] = rs[0]; }
}

__global__ void k_smax2(float* __restrict__ out) {
    int idx = blockIdx.x * 256 + threadIdx.x;
    int b = idx / 32000;
    float M = g_lm[b * 4];
    for (int cc = 1; cc < 4; cc++) M = fmaxf(M, g_lm[b * 4 + cc]);
    float L = 0.f;
    for (int cc = 0; cc < 4; cc++) L += g_ll[b * 4 + cc] * __expf(g_lm[b * 4 + cc] - M);
    out[idx] = __expf(out[idx] - M) / L;
}

extern "C" void kernel_launch(void* const* d_in, const int* in_sizes, int n_in,
                              void* d_out, int out_size) {
    const int*   ids  = (const int*)d_in[0];
    const float* lctx = (const float*)d_in[1];
    const float* hid  = (const float*)d_in[2];
    const float* enc  = (const float*)d_in[3];
    const float* emb  = (const float*)d_in[4];
    const float* Wat  = (const float*)d_in[5];
    const float* bat  = (const float*)d_in[6];
    const float* Wih0 = (const float*)d_in[7];
    const float* Whh0 = (const float*)d_in[8];
    const float* bih0 = (const float*)d_in[9];
    const float* bhh0 = (const float*)d_in[10];
    const float* Wih1 = (const float*)d_in[11];
    const float* Whh1 = (const float*)d_in[12];
    const float* bih1 = (const float*)d_in[13];
    const float* bhh1 = (const float*)d_in[14];
    const float* Wout = (const float*)d_in[15];
    const float* bout = (const float*)d_in[16];
    float* out    = (float*)d_out;
    float* o_sm   = out;
    float* o_ctx  = out + 1024000;
    float* o_hid  = out + 1024000 + 32768;
    float* o_attn = out + 1024000 + 32768 + 65536;

    k_embed<<<256, 256>>>(ids, lctx, emb);
    k_gemm2<<<dim3(24, 4, 2), 256>>>(Wih0, Whh0, hid, 1, 2048, 1024);
    k_gru<<<128, 256>>>(bih0, bhh0, hid, 4, 0, o_hid);
    k_gemm2<<<dim3(24, 4, 2), 256>>>(Wih1, Whh1, hid + 32768, 2, 1024, 1024);
    k_gru<<<128, 256>>>(bih1, bhh1, hid + 32768, 4, 1, o_hid + 32768);
    k_vproj<<<dim3(4, 8), 256>>>(Wat);
    k_vreduce<<<129, 256>>>(bat);
    k_attn_logits<<<762, 256>>>(enc, Wout, bout, o_sm);
    k_attn_final<<<32, 256>>>(o_ctx, o_attn);
    k_logits2<<<250, 256>>>(Wout, bout, o_sm);
    k_smax1<<<dim3(32, 4), 256>>>(o_sm);
    k_smax2<<<4000, 256>>>(o_sm);
}

// round 8
// speedup vs baseline: 1.3591x; 1.0524x over previous
#include <cuda_runtime.h>
#include <math.h>

#define SEQ 2048
#define HID 1024
#define VOC 32000

// ---- static scratch ----
__device__ float g_rnn_in[32 * 2048];
__device__ float g_rit[2048 * 32];          // rnn_in transposed [k][b]
__device__ float g_h0[32 * 1024];
__device__ float g_h0t[1024 * 32];          // h0 transposed
__device__ float g_hpt[2 * 1024 * 32];      // hidden transposed, both layers
__device__ float g_cat[32 * 2048];          // [h1 | context]
__device__ float g_xt[2048 * 32];           // transposed [k][b] of [h1|context]
__device__ float g_v[32 * 1024];
__device__ float g_vpart[8 * 32 * 1024];
__device__ float g_c[32];
__device__ float g_p[32 * 2048];            // raw scores
__device__ float g_pm[32 * 16];
__device__ float g_pl[32 * 16];
__device__ float g_pctx[32 * 16 * 1024];
__device__ float g_lm[32 * 4];
__device__ float g_ll[32 * 4];
__device__ float g_pi[8 * 32 * 3072];
__device__ float g_ph[8 * 32 * 3072];

// ---- packed f32x2 helpers ----
__device__ __forceinline__ void fma2(unsigned long long& d, unsigned long long a,
                                     unsigned long long x) {
    asm("fma.rn.f32x2 %0, %1, %2, %0;" : "+l"(d) : "l"(a), "l"(x));
}
__device__ __forceinline__ unsigned long long pack2(float a) {
    unsigned long long r;
    asm("mov.b64 %0, {%1, %1};" : "=l"(r) : "f"(a));
    return r;
}
__device__ __forceinline__ void unpack2(unsigned long long v, float& lo, float& hi) {
    asm("mov.b64 {%0, %1}, %2;" : "=f"(lo), "=f"(hi) : "l"(v));
}
// ---- cp.async helpers ----
__device__ __forceinline__ unsigned su32(const void* p) {
    unsigned a;
    asm("{ .reg .u64 t; cvta.to.shared.u64 t, %1; cvt.u32.u64 %0, t; }" : "=r"(a) : "l"(p));
    return a;
}
__device__ __forceinline__ void cp16(unsigned s, const void* g) {
    asm volatile("cp.async.ca.shared.global [%0], [%1], 16;" :: "r"(s), "l"(g));
}
__device__ __forceinline__ void cp_commit() {
    asm volatile("cp.async.commit_group;" ::: "memory");
}
__device__ __forceinline__ void cp_wait1() {
    asm volatile("cp.async.wait_group 1;" ::: "memory");
}
__device__ __forceinline__ void cp_wait0() {
    asm volatile("cp.async.wait_group 0;" ::: "memory");
}

// 1) embedding gather + concat (+transposes of rnn_in and hidden)
__global__ void k_embed(const int* __restrict__ ids, const float* __restrict__ lctx,
                        const float* __restrict__ hid, const float* __restrict__ emb) {
    int idx = blockIdx.x * 256 + threadIdx.x;   // 65536
    int b = idx >> 11, j = idx & 2047;
    float val = (j < HID) ? emb[(size_t)ids[b] * HID + j]
                          : lctx[b * HID + (j - HID)];
    g_rnn_in[idx] = val;
    g_rit[j * 32 + b] = val;
    // hidden transpose: idx spans 2*32*1024 = 65536 exactly
    int l2 = idx >> 15, rest = idx & 32767;
    int b2 = rest >> 10, h2 = rest & 1023;
    g_hpt[l2 * 32768 + h2 * 32 + b2] = hid[idx];
}

// ---- generic pipelined partial-GEMM body (A row-stride Kfull, Xt [k][b]) ----
__device__ __forceinline__ void gemm_body(float* sbuf, const float* __restrict__ A,
        const float* __restrict__ Xt, int Kfull, int mb, int j0, int j1,
        unsigned long long (&acc)[4][2]) {
    float* As = sbuf;               // 2 x 4608
    float* Xs = sbuf + 9216;        // 2 x 1152
    int tid = threadIdx.x;
    int tx = tid & 7, ty = tid >> 3;
    {
#pragma unroll
        for (int l = 0; l < 4; l++) {
            int idx = tid + 256 * l;
            int row = idx >> 3, q = idx & 7;
            cp16(su32(&As[row * 36 + q * 4]),
                 &A[(size_t)(mb + row) * Kfull + j0 * 32 + q * 4]);
        }
        int kk = tid >> 3, q = tid & 7;
        cp16(su32(&Xs[kk * 36 + q * 4]), &Xt[(j0 * 32 + kk) * 32 + q * 4]);
        cp_commit();
    }
    for (int j = j0; j < j1; j++) {
        int cur = (j - j0) & 1;
        if (j + 1 < j1) {
            int nb = 1 - cur;
#pragma unroll
            for (int l = 0; l < 4; l++) {
                int idx = tid + 256 * l;
                int row = idx >> 3, q = idx & 7;
                cp16(su32(&As[nb * 4608 + row * 36 + q * 4]),
                     &A[(size_t)(mb + row) * Kfull + (j + 1) * 32 + q * 4]);
            }
            int kk = tid >> 3, q = tid & 7;
            cp16(su32(&Xs[nb * 1152 + kk * 36 + q * 4]),
                 &Xt[((j + 1) * 32 + kk) * 32 + q * 4]);
            cp_commit();
            cp_wait1();
        } else {
            cp_wait0();
        }
        __syncthreads();
#pragma unroll
        for (int kk = 0; kk < 32; kk++) {
            unsigned long long x01 = *reinterpret_cast<const unsigned long long*>(
                &Xs[cur * 1152 + kk * 36 + tx * 4]);
            unsigned long long x23 = *reinterpret_cast<const unsigned long long*>(
                &Xs[cur * 1152 + kk * 36 + tx * 4 + 2]);
#pragma unroll
            for (int jj = 0; jj < 4; jj++) {
                unsigned long long a2 = pack2(As[cur * 4608 + (ty + 32 * jj) * 36 + kk]);
                fma2(acc[jj][0], a2, x01);
                fma2(acc[jj][1], a2, x23);
            }
        }
        __syncthreads();
    }
}

// 2) dual k-split GRU GEMM (pipelined): z2=0 -> gi (A0), z2=1 -> gh (A1)
__global__ __launch_bounds__(256) void k_gemm2(const float* __restrict__ A0,
        const float* __restrict__ A1, int xs0, int xs1, int K0, int K1) {
    __shared__ __align__(16) float sbuf[11520];
    int zz2 = blockIdx.z;
    const float* A = zz2 ? A1 : A0;
    int K = zz2 ? K1 : K0;
    int xsel = zz2 ? xs1 : xs0;
    const float* Xt = (xsel == 0) ? g_rit : (xsel == 1) ? g_hpt
                      : (xsel == 2) ? g_h0t : g_hpt + 32768;
    float* P = zz2 ? g_ph : g_pi;
    const int M = 3072;
    int z = blockIdx.y;
    int ntile = K / 256;            // K/32/8
    int j0 = z * ntile, j1 = j0 + ntile;
    int mb = blockIdx.x * 128;
    int tid = threadIdx.x, tx = tid & 7, ty = tid >> 3;
    unsigned long long acc[4][2];
#pragma unroll
    for (int jj = 0; jj < 4; jj++) { acc[jj][0] = 0ull; acc[jj][1] = 0ull; }
    gemm_body(sbuf, A, Xt, K, mb, j0, j1, acc);
    float* Pz = P + (size_t)z * 32 * M;
#pragma unroll
    for (int jj = 0; jj < 4; jj++) {
        int row = mb + ty + 32 * jj;
        float v0, v1, v2, v3;
        unpack2(acc[jj][0], v0, v1);
        unpack2(acc[jj][1], v2, v3);
        Pz[(size_t)(tx * 4 + 0) * M + row] = v0;
        Pz[(size_t)(tx * 4 + 1) * M + row] = v1;
        Pz[(size_t)(tx * 4 + 2) * M + row] = v2;
        Pz[(size_t)(tx * 4 + 3) * M + row] = v3;
    }
}

// 3) GRU combine (ks=8); layer0 writes g_h0t, layer1 writes g_xt
__global__ void k_gru(const float* __restrict__ bih, const float* __restrict__ bhh,
                      const float* __restrict__ hprev, int layer,
                      float* __restrict__ dout) {
    int idx = blockIdx.x * 256 + threadIdx.x;
    int b = idx >> 10, h = idx & 1023;
    const int M = 3072;
    float ir = bih[h], iz = bih[1024 + h], in = bih[2048 + h];
    float hr = bhh[h], hz = bhh[1024 + h], hn = bhh[2048 + h];
    for (int z = 0; z < 8; z++) {
        const float* pi = g_pi + (size_t)z * 32 * M + (size_t)b * M;
        const float* ph = g_ph + (size_t)z * 32 * M + (size_t)b * M;
        ir += pi[h]; iz += pi[1024 + h]; in += pi[2048 + h];
        hr += ph[h]; hz += ph[1024 + h]; hn += ph[2048 + h];
    }
    float r = 1.f / (1.f + __expf(-(ir + hr)));
    float zz = 1.f / (1.f + __expf(-(iz + hz)));
    float n = tanhf(in + r * hn);
    float outv = (1.f - zz) * n + zz * hprev[b * 1024 + h];
    if (layer == 0) { g_h0[idx] = outv; g_h0t[h * 32 + b] = outv; }
    else { g_cat[b * 2048 + h] = outv; g_xt[h * 32 + b] = outv; }
    dout[b * 1024 + h] = outv;
}

// 4) v = h1 @ W_attn (j-chunked, f32x2)
__global__ __launch_bounds__(256) void k_vproj(const float* __restrict__ W) {
    __shared__ __align__(16) float xs[128 * 34];
    int tid = threadIdx.x;
    int jc = blockIdx.y;
    for (int l = 0; l < 16; l++) {
        int idx = tid + 256 * l;
        int j = idx >> 5, b = idx & 31;
        xs[j * 34 + b] = g_cat[b * 2048 + jc * 128 + j];
    }
    __syncthreads();
    int k = blockIdx.x * 256 + tid;
    unsigned long long acc[16];
#pragma unroll
    for (int p = 0; p < 16; p++) acc[p] = 0ull;
    for (int j = 0; j < 128; j++) {
        unsigned long long w2 = pack2(W[(size_t)(jc * 128 + j) * 1024 + k]);
#pragma unroll
        for (int p = 0; p < 16; p++)
            fma2(acc[p], w2,
                 *reinterpret_cast<const unsigned long long*>(&xs[j * 34 + 2 * p]));
    }
#pragma unroll
    for (int p = 0; p < 16; p++) {
        float lo, hi;
        unpack2(acc[p], lo, hi);
        g_vpart[(size_t)jc * 32768 + (2 * p) * 1024 + k] = lo;
        g_vpart[(size_t)jc * 32768 + (2 * p + 1) * 1024 + k] = hi;
    }
}

// 5) v-reduce + cvec merged (block 128 does cvec)
__global__ void k_vreduce(const float* __restrict__ ba) {
    if (blockIdx.x == 128) {
        int w = threadIdx.x >> 5, lane = threadIdx.x & 31;
        for (int bq = 0; bq < 4; bq++) {
            int b = w * 4 + bq;
            float acc = 0.f;
            for (int j = lane; j < 1024; j += 32) acc += ba[j] * g_cat[b * 2048 + j];
            for (int o = 16; o; o >>= 1) acc += __shfl_xor_sync(~0u, acc, o);
            if (!lane) g_c[b] = acc;
        }
        return;
    }
    int idx = blockIdx.x * 256 + threadIdx.x;
    float s = 0.f;
    for (int jc = 0; jc < 8; jc++) s += g_vpart[(size_t)jc * 32768 + idx];
    g_v[idx] = s;
}

// ---- logits epilogue wrapper ----
__device__ __forceinline__ void logits_tail(unsigned long long (&acc)[4][2],
        const float* __restrict__ bout, float* __restrict__ out, int mb, bool acc_mode) {
    int tid = threadIdx.x, tx = tid & 7, ty = tid >> 3;
#pragma unroll
    for (int jj = 0; jj < 4; jj++) {
        int row = mb + ty + 32 * jj;
        float v0, v1, v2, v3;
        unpack2(acc[jj][0], v0, v1);
        unpack2(acc[jj][1], v2, v3);
        if (acc_mode) {
            out[(size_t)(tx * 4 + 0) * VOC + row] += v0;
            out[(size_t)(tx * 4 + 1) * VOC + row] += v1;
            out[(size_t)(tx * 4 + 2) * VOC + row] += v2;
            out[(size_t)(tx * 4 + 3) * VOC + row] += v3;
        } else {
            float bias = bout[row];
            out[(size_t)(tx * 4 + 0) * VOC + row] = v0 + bias;
            out[(size_t)(tx * 4 + 1) * VOC + row] = v1 + bias;
            out[(size_t)(tx * 4 + 2) * VOC + row] = v2 + bias;
            out[(size_t)(tx * 4 + 3) * VOC + row] = v3 + bias;
        }
    }
}

// 6) fused: blocks 0..511 flash attention; blocks 512..761 logits h1-half
__global__ __launch_bounds__(256) void k_attn_logits(const float* __restrict__ enc,
        const float* __restrict__ Wout, const float* __restrict__ bout,
        float* __restrict__ out_sm) {
    __shared__ __align__(16) float sbuf[11520];
    __shared__ float ssc[8];
    int bid = blockIdx.x;
    if (bid >= 512) {
        int mb = (bid - 512) * 128;
        unsigned long long acc[4][2];
#pragma unroll
        for (int jj = 0; jj < 4; jj++) { acc[jj][0] = 0ull; acc[jj][1] = 0ull; }
        gemm_body(sbuf, Wout, g_xt, 2048, mb, 0, 32, acc);
        logits_tail(acc, bout, out_sm, mb, false);
        return;
    }
    int c = bid & 15, b = bid >> 4;
    float* srow = sbuf;
    int tid = threadIdx.x, w = tid >> 5, lane = tid & 31;
    const float4* v4 = reinterpret_cast<const float4*>(g_v + b * 1024);
    float4 vf[8];
#pragma unroll
    for (int j = 0; j < 8; j++) vf[j] = v4[lane + 32 * j];
    float cb = g_c[b];
    float m = -1e30f, l = 0.f;
    float c0 = 0.f, c1 = 0.f, c2 = 0.f, c3 = 0.f;
    const float4* enc4 = reinterpret_cast<const float4*>(enc);
    float4* srow4 = reinterpret_cast<float4*>(srow);
    float4 e[8];
    {
        size_t base = ((size_t)b * SEQ + c * 128 + w) * 256;
#pragma unroll
        for (int j = 0; j < 8; j++) e[j] = enc4[base + lane + 32 * j];
    }
    for (int sub = 0; sub < 16; sub++) {
        int row0 = c * 128 + sub * 8;
        float acc = 0.f;
#pragma unroll
        for (int j = 0; j < 8; j++) {
            srow4[w * 256 + lane + 32 * j] = e[j];
            acc += e[j].x * vf[j].x + e[j].y * vf[j].y + e[j].z * vf[j].z + e[j].w * vf[j].w;
        }
        for (int o = 16; o; o >>= 1) acc += __shfl_xor_sync(~0u, acc, o);
        if (!lane) {
            float s = acc + cb;
            ssc[w] = s;
            g_p[b * SEQ + row0 + w] = s;
        }
        __syncthreads();
        if (sub < 15) {
            size_t nb = ((size_t)b * SEQ + row0 + 8 + w) * 256;
#pragma unroll
            for (int j = 0; j < 8; j++) e[j] = enc4[nb + lane + 32 * j];
        }
        float mloc = ssc[0];
#pragma unroll
        for (int r = 1; r < 8; r++) mloc = fmaxf(mloc, ssc[r]);
        float mnew = fmaxf(m, mloc);
        float f = __expf(m - mnew);
        l *= f; c0 *= f; c1 *= f; c2 *= f; c3 *= f;
#pragma unroll
        for (int r = 0; r < 8; r++) {
            float p = __expf(ssc[r] - mnew);
            l += p;
            c0 += p * srow[r * 1024 + tid];
            c1 += p * srow[r * 1024 + tid + 256];
            c2 += p * srow[r * 1024 + tid + 512];
            c3 += p * srow[r * 1024 + tid + 768];
        }
        m = mnew;
        __syncthreads();
    }
    size_t ci = (size_t)(b * 16 + c) * 1024;
    g_pctx[ci + tid] = c0;       g_pctx[ci + tid + 256] = c1;
    g_pctx[ci + tid + 512] = c2; g_pctx[ci + tid + 768] = c3;
    if (!tid) { g_pm[b * 16 + c] = m; g_pl[b * 16 + c] = l; }
}

// 7) attention combine: context (+g_xt transposed) + normalized weights
__global__ void k_attn_final(float* __restrict__ out_ctx, float* __restrict__ out_attn) {
    int b = blockIdx.x, tid = threadIdx.x;
    float M = g_pm[b * 16];
    for (int cc = 1; cc < 16; cc++) M = fmaxf(M, g_pm[b * 16 + cc]);
    float L = 0.f, f[16];
    for (int cc = 0; cc < 16; cc++) {
        f[cc] = __expf(g_pm[b * 16 + cc] - M);
        L += g_pl[b * 16 + cc] * f[cc];
    }
    float inv = 1.f / L;
    for (int q = 0; q < 4; q++) {
        int h = tid + 256 * q;
        float s = 0.f;
        for (int cc = 0; cc < 16; cc++)
            s += g_pctx[(size_t)(b * 16 + cc) * 1024 + h] * f[cc];
        s *= inv;
        out_ctx[b * 1024 + h] = s;
        g_xt[(1024 + h) * 32 + b] = s;
    }
    for (int s = tid; s < 2048; s += 256)
        out_attn[b * 2048 + s] = __expf(g_p[b * 2048 + s] - M) * inv;
}

// 8) logits phase 2: context half, accumulate into out
__global__ __launch_bounds__(256) void k_logits2(const float* __restrict__ Wout,
        const float* __restrict__ bout, float* __restrict__ out) {
    __shared__ __align__(16) float sbuf[11520];
    int mb = blockIdx.x * 128;
    unsigned long long acc[4][2];
#pragma unroll
    for (int jj = 0; jj < 4; jj++) { acc[jj][0] = 0ull; acc[jj][1] = 0ull; }
    gemm_body(sbuf, Wout, g_xt, 2048, mb, 32, 64, acc);
    logits_tail(acc, bout, out, mb, true);
}

// 9) softmax over vocab (chunked)
__global__ void k_smax1(const float* __restrict__ logits) {
    int b = blockIdx.x, cc = blockIdx.y, tid = threadIdx.x;
    __shared__ float rs[256];
    const float* base = logits + (size_t)b * 32000 + cc * 8000;
    float m = -1e30f;
    for (int i = tid; i < 8000; i += 256) m = fmaxf(m, base[i]);
    rs[tid] = m; __syncthreads();
    for (int o = 128; o; o >>= 1) { if (tid < o) rs[tid] = fmaxf(rs[tid], rs[tid + o]); __syncthreads(); }
    m = rs[0]; __syncthreads();
    float l = 0.f;
    for (int i = tid; i < 8000; i += 256) l += __expf(base[i] - m);
    rs[tid] = l; __syncthreads();
    for (int o = 128; o; o >>= 1) { if (tid < o) rs[tid] += rs[tid + o]; __syncthreads(); }
    if (!tid) { g_lm[b * 4 + cc] = m; g_ll[b * 4 + cc] = rs[0]; }
}

__global__ void k_smax2(float* __restrict__ out) {
    int idx = blockIdx.x * 256 + threadIdx.x;
    int b = idx / 32000;
    float M = g_lm[b * 4];
    for (int cc = 1; cc < 4; cc++) M = fmaxf(M, g_lm[b * 4 + cc]);
    float L = 0.f;
    for (int cc = 0; cc < 4; cc++) L += g_ll[b * 4 + cc] * __expf(g_lm[b * 4 + cc] - M);
    out[idx] = __expf(out[idx] - M) / L;
}

extern "C" void kernel_launch(void* const* d_in, const int* in_sizes, int n_in,
                              void* d_out, int out_size) {
    const int*   ids  = (const int*)d_in[0];
    const float* lctx = (const float*)d_in[1];
    const float* hid  = (const float*)d_in[2];
    const float* enc  = (const float*)d_in[3];
    const float* emb  = (const float*)d_in[4];
    const float* Wat  = (const float*)d_in[5];
    const float* bat  = (const float*)d_in[6];
    const float* Wih0 = (const float*)d_in[7];
    const float* Whh0 = (const float*)d_in[8];
    const float* bih0 = (const float*)d_in[9];
    const float* bhh0 = (const float*)d_in[10];
    const float* Wih1 = (const float*)d_in[11];
    const float* Whh1 = (const float*)d_in[12];
    const float* bih1 = (const float*)d_in[13];
    const float* bhh1 = (const float*)d_in[14];
    const float* Wout = (const float*)d_in[15];
    const float* bout = (const float*)d_in[16];
    float* out    = (float*)d_out;
    float* o_sm   = out;
    float* o_ctx  = out + 1024000;
    float* o_hid  = out + 1024000 + 32768;
    float* o_attn = out + 1024000 + 32768 + 65536;

    k_embed<<<256, 256>>>(ids, lctx, hid, emb);
    k_gemm2<<<dim3(24, 8, 2), 256>>>(Wih0, Whh0, 0, 1, 2048, 1024);
    k_gru<<<128, 256>>>(bih0, bhh0, hid, 0, o_hid);
    k_gemm2<<<dim3(24, 8, 2), 256>>>(Wih1, Whh1, 2, 3, 1024, 1024);
    k_gru<<<128, 256>>>(bih1, bhh1, hid + 32768, 1, o_hid + 32768);
    k_vproj<<<dim3(4, 8), 256>>>(Wat);
    k_vreduce<<<129, 256>>>(bat);
    k_attn_logits<<<762, 256>>>(enc, Wout, bout, o_sm);
    k_attn_final<<<32, 256>>>(o_ctx, o_attn);
    k_logits2<<<250, 256>>>(Wout, bout, o_sm);
    k_smax1<<<dim3(32, 4), 256>>>(o_sm);
    k_smax2<<<4000, 256>>>(o_sm);
}